// round 12
// baseline (speedup 1.0000x reference)
#include <cuda_runtime.h>
#include <cuda_fp16.h>

#define HDIM   64
#define NHEADS 4
#define QKDIM  256           // NHEADS * HDIM
#define N_SRC  50000
#define N_TGT  10000
#define N_E    250000
#define N_LBL  200000

#define PADK   72            // smem row stride in fp16 (144B): ldmatrix conflict-free
#define WSECT  (832 * 64)    // per (layer,edge_type) transposed weight block (elements)
#define NBS    391           // (N_SRC+127)/128
#define NBT    79            // (N_TGT+127)/128

// ---------------- scratch (static device memory; no allocations) ----------------
__device__ float g_xs_a[N_SRC * HDIM];
__device__ float g_xs_b[N_SRC * HDIM];
__device__ float g_xt_a[N_TGT * HDIM];
__device__ float g_xt_b[N_TGT * HDIM];

__device__ __align__(16) __half g_q_st[N_TGT * QKDIM];
__device__ __align__(16) __half g_k_ts[N_TGT * QKDIM];
__device__ __align__(16) __half g_v_ts[N_TGT * QKDIM];
__device__ __align__(16) __half g_q_ts[N_SRC * QKDIM];
__device__ __align__(16) __half g_k_st[N_SRC * QKDIM];
__device__ __align__(16) __half g_v_st[N_SRC * QKDIM];

__device__ float g_sc_st[N_E * NHEADS];
__device__ float g_sc_ts[N_E * NHEADS];
__device__ float g_d_st[N_TGT * NHEADS];
__device__ float g_d_ts[N_SRC * NHEADS];

// A operand: fp16. B: split-fp16 (hi + residual).
__device__ __align__(16) __half g_xsh[N_SRC * HDIM];
__device__ __align__(16) __half g_xth[N_TGT * HDIM];
__device__ __align__(16) __half g_wth[4 * WSECT];
__device__ __align__(16) __half g_wtl[4 * WSECT];

// ---------------- helpers ----------------
__device__ __forceinline__ void split2h(float v, __half& h, __half& l) {
    h = __float2half_rn(v);
    l = __float2half_rn(v - __half2float(h));
}
__device__ __forceinline__ unsigned su32(const void* p) {
    unsigned a;
    asm("{ .reg .u64 t; cvta.to.shared.u64 t, %1; cvt.u32.u64 %0, t; }" : "=r"(a) : "l"(p));
    return a;
}
__device__ __forceinline__ void ldsm4(unsigned& r0, unsigned& r1, unsigned& r2, unsigned& r3,
                                      unsigned addr) {
    asm volatile("ldmatrix.sync.aligned.m8n8.x4.shared.b16 {%0,%1,%2,%3}, [%4];"
                 : "=r"(r0), "=r"(r1), "=r"(r2), "=r"(r3) : "r"(addr));
}
__device__ __forceinline__ void mma16816h(float* d, const unsigned* a, unsigned b0, unsigned b1) {
    asm volatile("mma.sync.aligned.m16n8k16.row.col.f32.f16.f16.f32 "
                 "{%0,%1,%2,%3}, {%4,%5,%6,%7}, {%8,%9}, {%0,%1,%2,%3};"
                 : "+f"(d[0]), "+f"(d[1]), "+f"(d[2]), "+f"(d[3])
                 : "r"(a[0]), "r"(a[1]), "r"(a[2]), "r"(a[3]), "r"(b0), "r"(b1));
}
__device__ __forceinline__ float dot8h(uint4 qa, uint4 ka) {
    const __half2* qh = (const __half2*)&qa;
    const __half2* kh = (const __half2*)&ka;
    float dot = 0.0f;
    #pragma unroll
    for (int i = 0; i < 4; i++) {
        float2 a = __half22float2(qh[i]);
        float2 b = __half22float2(kh[i]);
        dot += a.x * b.x + a.y * b.y;
    }
    return dot;
}

// ---------------- small kernels ----------------
__global__ void zero2_kernel(float* __restrict__ a, int na, float* __restrict__ b, int nb) {
    int i = blockIdx.x * blockDim.x + threadIdx.x;
    if (i < na) { a[i] = 0.0f; return; }
    i -= na;
    if (i < nb) b[i] = 0.0f;
}

__global__ void gather_h2(const float* __restrict__ semb, const float* __restrict__ temb,
                          const int* __restrict__ sid, const int* __restrict__ tid) {
    int i = blockIdx.x * blockDim.x + threadIdx.x;
    if (i < N_SRC * HDIM) {
        int row = i >> 6, d = i & 63;
        g_xsh[i] = __float2half_rn(semb[(size_t)sid[row] * HDIM + d]);
    } else if (i < (N_SRC + N_TGT) * HDIM) {
        int j = i - N_SRC * HDIM;
        int row = j >> 6, d = j & 63;
        g_xth[j] = __float2half_rn(temb[(size_t)tid[row] * HDIM + d]);
    }
}

// both relu conversions in one launch (layer-1 input prep)
__global__ void relu_h2() {
    int i = blockIdx.x * blockDim.x + threadIdx.x;
    if (i < N_SRC * HDIM) {
        g_xsh[i] = __float2half_rn(fmaxf(g_xs_b[i], 0.0f));
    } else if (i < (N_SRC + N_TGT) * HDIM) {
        int j = i - N_SRC * HDIM;
        g_xth[j] = __float2half_rn(fmaxf(g_xt_b[j], 0.0f));
    }
}

__global__ void split_w(const float* __restrict__ Wq, const float* __restrict__ Wk,
                        const float* __restrict__ Wv, const float* __restrict__ Ws) {
    int i = blockIdx.x * blockDim.x + threadIdx.x;
    if (i >= 4 * WSECT) return;
    int le = i / WSECT, rem = i % WSECT;
    int n = rem >> 6, k = rem & 63;
    float v;
    if (n < 256)      v = Wq[(size_t)le * 64 * 256 + k * 256 + n];
    else if (n < 512) v = Wk[(size_t)le * 64 * 256 + k * 256 + (n - 256)];
    else if (n < 768) v = Wv[(size_t)le * 64 * 256 + k * 256 + (n - 512)];
    else              v = Ws[(size_t)le * 64 * 64 + k * 64 + (n - 768)];
    split2h(v, g_wth[i], g_wtl[i]);
}

// ---------------- fused projection: src + tgt sides in ONE launch ----------------
// grid = (NBS + NBT, 4). blockIdx.x < NBS -> src side, else tgt side.
// sections: 0/1/2 -> fp16 q/k/v-type outputs (4 col-blocks), 3 -> fp32 skip (1).
__global__ void __launch_bounds__(256) proj_all(
    int l, const float* __restrict__ bq, const float* __restrict__ bk,
    const float* __restrict__ bv, const float* __restrict__ bs) {
    extern __shared__ __half sm[];
    __half* Ah = sm;                           // [128][PADK]
    __half* Bh = Ah + 128 * PADK;              // [64][PADK]
    __half* Bl = Bh + 64 * PADK;

    int le0 = l * 2, le1 = l * 2 + 1;
    bool src_side = blockIdx.x < NBS;
    int bx = src_side ? blockIdx.x : blockIdx.x - NBS;
    const __half* X = src_side ? g_xsh : g_xth;
    int N = src_side ? N_SRC : N_TGT;
    int sec = blockIdx.y;

    int woff; const float* bias; __half* outh = 0; float* outf = 0; int ncb;
    if (src_side) {
        if (sec == 0)      { woff = le0 * WSECT + 256 * 64; bias = bk + le0 * 256; outh = g_k_st; ncb = 4; }
        else if (sec == 1) { woff = le0 * WSECT + 512 * 64; bias = bv + le0 * 256; outh = g_v_st; ncb = 4; }
        else if (sec == 2) { woff = le1 * WSECT;            bias = bq + le1 * 256; outh = g_q_ts; ncb = 4; }
        else               { woff = le1 * WSECT + 768 * 64; bias = bs + le1 * 64;
                             outf = l ? g_xs_a : g_xs_b; ncb = 1; }
    } else {
        if (sec == 0)      { woff = le0 * WSECT;            bias = bq + le0 * 256; outh = g_q_st; ncb = 4; }
        else if (sec == 1) { woff = le1 * WSECT + 256 * 64; bias = bk + le1 * 256; outh = g_k_ts; ncb = 4; }
        else if (sec == 2) { woff = le1 * WSECT + 512 * 64; bias = bv + le1 * 256; outh = g_v_ts; ncb = 4; }
        else               { woff = le0 * WSECT + 768 * 64; bias = bs + le0 * 64;
                             outf = l ? g_xt_a : g_xt_b; ncb = 1; }
    }

    int t = threadIdx.x;
    int rowbase = bx * 128;

    // stage A once (fp16)
    const uint4* xh4 = (const uint4*)X;
    uint4 z4 = make_uint4(0u, 0u, 0u, 0u);
    #pragma unroll
    for (int i = 0; i < 4; i++) {
        int idx = t + i * 256;
        int r = idx >> 3, c = idx & 7;
        int gr = rowbase + r;
        uint4 vh = z4;
        if (gr < N) vh = xh4[(size_t)gr * 8 + c];
        *(uint4*)(Ah + r * PADK + c * 8) = vh;
    }

    int lane = t & 31, warp = t >> 5;
    int wr = warp >> 1, wc = warp & 1;
    int lrow = lane & 7, lsel = lane >> 3;
    unsigned ah_u = su32(Ah), bh_u = su32(Bh), bl_u = su32(Bl);

    for (int lcb = 0; lcb < ncb; lcb++) {
        if (lcb) __syncthreads();
        int wo = woff + lcb * 64 * 64;
        const uint4* wh4 = (const uint4*)(g_wth + wo);
        const uint4* wl4 = (const uint4*)(g_wtl + wo);
        #pragma unroll
        for (int i = 0; i < 2; i++) {
            int idx = t + i * 256;
            int n = idx >> 3, c = idx & 7;
            *(uint4*)(Bh + n * PADK + c * 8) = wh4[n * 8 + c];
            *(uint4*)(Bl + n * PADK + c * 8) = wl4[n * 8 + c];
        }
        __syncthreads();

        float acc[2][4][4];
        #pragma unroll
        for (int mt = 0; mt < 2; mt++)
            #pragma unroll
            for (int nt = 0; nt < 4; nt++)
                #pragma unroll
                for (int r = 0; r < 4; r++) acc[mt][nt][r] = 0.0f;

        #pragma unroll
        for (int kc = 0; kc < 4; kc++) {
            int k0 = kc * 16;
            unsigned ah[2][4], bh[2][4], bl[2][4];
            #pragma unroll
            for (int mt = 0; mt < 2; mt++) {
                int row = wr * 32 + mt * 16 + (lsel & 1) * 8 + lrow;
                int koff = k0 + (lsel >> 1) * 8;
                unsigned boff = (unsigned)(row * PADK + koff) * 2u;
                ldsm4(ah[mt][0], ah[mt][1], ah[mt][2], ah[mt][3], ah_u + boff);
            }
            #pragma unroll
            for (int nt2 = 0; nt2 < 2; nt2++) {
                int n = wc * 32 + nt2 * 16 + (lsel >> 1) * 8 + lrow;
                int koff = k0 + (lsel & 1) * 8;
                unsigned boff = (unsigned)(n * PADK + koff) * 2u;
                ldsm4(bh[nt2][0], bh[nt2][1], bh[nt2][2], bh[nt2][3], bh_u + boff);
                ldsm4(bl[nt2][0], bl[nt2][1], bl[nt2][2], bl[nt2][3], bl_u + boff);
            }
            #pragma unroll
            for (int mt = 0; mt < 2; mt++)
                #pragma unroll
                for (int nt = 0; nt < 4; nt++) {
                    int g = nt >> 1, hf = (nt & 1) * 2;
                    mma16816h(acc[mt][nt], ah[mt], bh[g][hf], bh[g][hf + 1]);
                    mma16816h(acc[mt][nt], ah[mt], bl[g][hf], bl[g][hf + 1]);
                }
        }

        #pragma unroll
        for (int mt = 0; mt < 2; mt++) {
            int ra = rowbase + wr * 32 + mt * 16 + (lane >> 2);
            int rb = ra + 8;
            #pragma unroll
            for (int nt = 0; nt < 4; nt++) {
                int col = lcb * 64 + wc * 32 + nt * 8 + (lane & 3) * 2;
                float2 bv2 = *(const float2*)(bias + col);
                if (sec < 3) {
                    if (ra < N)
                        *(__half2*)(outh + (size_t)ra * 256 + col) =
                            __floats2half2_rn(acc[mt][nt][0] + bv2.x, acc[mt][nt][1] + bv2.y);
                    if (rb < N)
                        *(__half2*)(outh + (size_t)rb * 256 + col) =
                            __floats2half2_rn(acc[mt][nt][2] + bv2.x, acc[mt][nt][3] + bv2.y);
                } else {
                    if (ra < N)
                        *(float2*)(outf + (size_t)ra * 64 + col) =
                            make_float2(acc[mt][nt][0] + bv2.x, acc[mt][nt][1] + bv2.y);
                    if (rb < N)
                        *(float2*)(outf + (size_t)rb * 64 + col) =
                            make_float2(acc[mt][nt][2] + bv2.x, acc[mt][nt][3] + bv2.y);
                }
            }
        }
    }
}

// ---------------- fused score+exp+denom: BOTH directions in one launch ----------------
__global__ void scoreexp2(const int* __restrict__ e_st, const int* __restrict__ e_ts) {
    int gw = (blockIdx.x * blockDim.x + threadIdx.x) >> 5;
    if (gw >= 2 * N_E) return;
    int lane = threadIdx.x & 31;
    bool st = gw < N_E;
    int e = st ? gw : gw - N_E;
    const int* eidx = st ? e_st : e_ts;
    const __half* q = st ? g_q_st : g_q_ts;
    const __half* k = st ? g_k_st : g_k_ts;
    float* score = st ? g_sc_st : g_sc_ts;
    float* denom = st ? g_d_st : g_d_ts;

    int s = eidx[e], d = eidx[N_E + e];
    int h = lane >> 3, sub = lane & 7;
    uint4 qa = *(const uint4*)(q + (size_t)d * QKDIM + h * HDIM + sub * 8);
    uint4 ka = *(const uint4*)(k + (size_t)s * QKDIM + h * HDIM + sub * 8);
    float dot = dot8h(qa, ka);
    dot += __shfl_down_sync(0xffffffffu, dot, 4, 8);
    dot += __shfl_down_sync(0xffffffffu, dot, 2, 8);
    dot += __shfl_down_sync(0xffffffffu, dot, 1, 8);
    if (sub == 0) {
        float ex = __expf(dot * 0.125f);
        score[(size_t)e * NHEADS + h] = ex;
        atomicAdd(&denom[(size_t)d * NHEADS + h], ex);
    }
}

// ---------------- aggregation: BOTH directions in one launch ----------------
__global__ void agg2(const int* __restrict__ e_st, const int* __restrict__ e_ts, int l) {
    int gw = (blockIdx.x * blockDim.x + threadIdx.x) >> 5;
    if (gw >= 2 * N_E) return;
    int lane = threadIdx.x & 31;
    bool st = gw < N_E;
    int e = st ? gw : gw - N_E;
    const int* eidx = st ? e_st : e_ts;
    const float* sc = st ? g_sc_st : g_sc_ts;
    const float* den = st ? g_d_st : g_d_ts;
    const __half* v = st ? g_v_st : g_v_ts;
    float* out = st ? (l ? g_xt_a : g_xt_b) : (l ? g_xs_a : g_xs_b);

    int s = eidx[e], d = eidx[N_E + e];
    size_t eb = (size_t)e * NHEADS, db = (size_t)d * NHEADS;
    float a0 = sc[eb + 0] / den[db + 0];
    float a1 = sc[eb + 1] / den[db + 1];
    float a2 = sc[eb + 2] / den[db + 2];
    float a3 = sc[eb + 3] / den[db + 3];
    const __half2* vp = (const __half2*)(v + (size_t)s * QKDIM);
    float2 v0 = __half22float2(vp[lane]);
    float2 v1 = __half22float2(vp[32 + lane]);
    float2 v2 = __half22float2(vp[64 + lane]);
    float2 v3 = __half22float2(vp[96 + lane]);
    float ax = 0.25f * (a0 * v0.x + a1 * v1.x + a2 * v2.x + a3 * v3.x);
    float ay = 0.25f * (a0 * v0.y + a1 * v1.y + a2 * v2.y + a3 * v3.y);
    atomicAdd(&out[(size_t)d * HDIM + lane * 2 + 0], ax);
    atomicAdd(&out[(size_t)d * HDIM + lane * 2 + 1], ay);
}

// ---------------- classifier ----------------
__global__ void pred_kernel(const int* __restrict__ l0, const int* __restrict__ l1,
                            const float* __restrict__ xs, const float* __restrict__ xt,
                            float* __restrict__ out, int n) {
    int gid = blockIdx.x * blockDim.x + threadIdx.x;
    int pair = gid >> 3, sub = gid & 7;
    if (pair >= n) return;
    int a = l0[pair], b = l1[pair];
    const float4* xa = (const float4*)(xs + (size_t)a * HDIM);
    const float4* xb = (const float4*)(xt + (size_t)b * HDIM);
    float4 p0 = xa[sub * 2], p1 = xa[sub * 2 + 1];
    float4 q0 = xb[sub * 2], q1 = xb[sub * 2 + 1];
    float dot = p0.x * q0.x + p0.y * q0.y + p0.z * q0.z + p0.w * q0.w
              + p1.x * q1.x + p1.y * q1.y + p1.z * q1.z + p1.w * q1.w;
    dot += __shfl_down_sync(0xffffffffu, dot, 4, 8);
    dot += __shfl_down_sync(0xffffffffu, dot, 2, 8);
    dot += __shfl_down_sync(0xffffffffu, dot, 1, 8);
    if (sub == 0) out[pair] = dot;
}

// ---------------- launch ----------------
extern "C" void kernel_launch(void* const* d_in, const int* in_sizes, int n_in,
                              void* d_out, int out_size) {
    const float* src_emb = (const float*)d_in[0];
    const float* tgt_emb = (const float*)d_in[1];
    const float* Wq = (const float*)d_in[2];
    const float* bq = (const float*)d_in[3];
    const float* Wk = (const float*)d_in[4];
    const float* bk = (const float*)d_in[5];
    const float* Wv = (const float*)d_in[6];
    const float* bv = (const float*)d_in[7];
    const float* Ws = (const float*)d_in[8];
    const float* bs = (const float*)d_in[9];
    const int* nid_s = (const int*)d_in[10];
    const int* nid_t = (const int*)d_in[11];
    const int* e_st  = (const int*)d_in[12];
    const int* e_ts  = (const int*)d_in[13];
    const int* lbl   = (const int*)d_in[14];
    float* out = (float*)d_out;

    float *xs_a, *xt_a, *d_st, *d_ts;
    cudaGetSymbolAddress((void**)&xs_a, g_xs_a);
    cudaGetSymbolAddress((void**)&xt_a, g_xt_a);
    cudaGetSymbolAddress((void**)&d_st, g_d_st);
    cudaGetSymbolAddress((void**)&d_ts, g_d_ts);

    const int SMEM = (128 * PADK + 64 * PADK * 2) * 2;  // 36864 B
    cudaFuncSetAttribute(proj_all, cudaFuncAttributeMaxDynamicSharedMemorySize, SMEM);

    int nz0 = (N_TGT + N_SRC) * NHEADS;
    int nx = (N_SRC + N_TGT) * HDIM;
    zero2_kernel<<<(nz0 + 255) / 256, 256>>>(d_st, N_TGT * NHEADS, d_ts, N_SRC * NHEADS);
    gather_h2<<<(nx + 255) / 256, 256>>>(src_emb, tgt_emb, nid_s, nid_t);
    split_w<<<(4 * WSECT + 255) / 256, 256>>>(Wq, Wk, Wv, Ws);

    int eb2 = (2 * N_E * 32 + 255) / 256;  // one warp per edge, both directions

    for (int l = 0; l < 2; l++) {
        if (l) {
            relu_h2<<<(nx + 255) / 256, 256>>>();
            zero2_kernel<<<(nz0 + 255) / 256, 256>>>(d_st, N_TGT * NHEADS, d_ts, N_SRC * NHEADS);
        }

        dim3 gall(NBS + NBT, 4);
        proj_all<<<gall, 256, SMEM>>>(l, bq, bk, bv, bs);

        scoreexp2<<<eb2, 256>>>(e_st, e_ts);
        agg2<<<eb2, 256>>>(e_st, e_ts, l);
    }

    pred_kernel<<<(N_LBL * 8 + 255) / 256, 256>>>(lbl, lbl + N_LBL, xs_a, xt_a, out, N_LBL);
}